// round 12
// baseline (speedup 1.0000x reference)
#include <cuda_runtime.h>
#include <cuda_fp16.h>
#include <math.h>
#include <stdint.h>

// ---------------- constants ----------------
#define kS   1024
#define kD   2048
#define kH   32
#define kHD  64
#define kF   8192
#define kNE  4
#define kVOC 50257

// ---------------- scratch ----------------
__device__ __half g_wqh[kD*kD];
__device__ __half g_wkh[kD*kD];
__device__ __half g_wvh[kD*kD];
__device__ __half g_woh[kD*kD];
__device__ __half g_w1h[kNE*kF*kD];
__device__ __half g_w3h[kNE*kF*kD];
__device__ __half g_w2h[kNE*kD*kF];
__device__ __half g_hdh[kVOC*kD];
__device__ __half g_x0h [kS*kD];
__device__ __half g_qkvh[kS*3*kD];
__device__ __half g_oh  [kS*kD];
__device__ __half g_xn1h[kS*kD];
__device__ __half g_hah [kS*kNE*kF];
__device__ __half g_hbh [kS*kNE*kF];
__device__ __half g_x4h [kS*kD];
__device__ float g_part[2*kS*3*kD];
__device__ float g_wdense[kS*kNE];
__device__ float g_var[kS];

// ---------------- PTX helpers ----------------
__device__ __forceinline__ uint32_t smem_u32(const void* p) {
    uint32_t a;
    asm("{ .reg .u64 t; cvta.to.shared.u64 t, %1; cvt.u32.u64 %0, t; }" : "=r"(a) : "l"(p));
    return a;
}
__device__ __forceinline__ void cpa16(uint32_t dst, const void* src) {
    asm volatile("cp.async.cg.shared.global [%0], [%1], 16;" :: "r"(dst), "l"(src));
}
#define CPA_COMMIT() asm volatile("cp.async.commit_group;" ::: "memory")
#define CPA_WAIT1()  asm volatile("cp.async.wait_group 1;" ::: "memory")

#define LDSM_X4(r, addr) \
    asm volatile("ldmatrix.sync.aligned.m8n8.x4.shared.b16 {%0,%1,%2,%3}, [%4];" \
        : "=r"((r)[0]), "=r"((r)[1]), "=r"((r)[2]), "=r"((r)[3]) : "r"(addr))

__device__ __forceinline__ void mma_f16(float* c, const uint32_t* a, uint32_t b0, uint32_t b1) {
    asm volatile("mma.sync.aligned.m16n8k16.row.col.f32.f16.f16.f32 "
        "{%0,%1,%2,%3}, {%4,%5,%6,%7}, {%8,%9}, {%0,%1,%2,%3};"
        : "+f"(c[0]), "+f"(c[1]), "+f"(c[2]), "+f"(c[3])
        : "r"(a[0]), "r"(a[1]), "r"(a[2]), "r"(a[3]), "r"(b0), "r"(b1));
}

// ---------------- fp16 mma.sync NT GEMM: 128x128 tile, 4 warps (2x2), warp 64x64 ------
#define BM 128
#define BN 128
#define BKH 64
#define NSTG 3
#define ASTG 16384
#define STGB 32768
#define GEMM_SMEM (NSTG*STGB)

__global__ void __launch_bounds__(128, 2) gemm_h(
    const __half* __restrict__ A,
    const __half* __restrict__ B0, const __half* __restrict__ B1,
    const __half* __restrict__ B2, const __half* __restrict__ B3,
    float* __restrict__ Cf, __half* __restrict__ Ch,
    int N, int KT, int ldA, int ldB, int ldC,
    int nShift, int kShift, int ktPerZ, long long zStrideC,
    int fmode, const __half* __restrict__ F, int ldF,
    const float* __restrict__ wdense)
{
    extern __shared__ char smraw[];
    uint32_t sb = smem_u32(smraw);
    int tid = threadIdx.x, lane = tid & 31, wid = tid >> 5;
    int wm = wid >> 1, wn = wid & 1;                   // 2x2 warp grid, warp tile 64x64
    int bm = blockIdx.x * BM, bn = blockIdx.y * BN;

    Cf += (long long)blockIdx.z * zStrideC;
    int ktBeg = blockIdx.z * ktPerZ;
    int KTz = KT - ktBeg; if (KTz > ktPerZ) KTz = ktPerZ;

    const __half* BnBase;
    {
        int seg = bn >> nShift;
        const __half* bp = (seg == 0) ? B0 : (seg == 1) ? B1 : (seg == 2) ? B2 : B3;
        BnBase = bp + (size_t)(bn - (seg << nShift)) * ldB;
    }

    auto load_stage = [&](int s, int kt) {
        int ktl = kt;
        const __half* Bb = BnBase;
        if (kShift >= 0) {
            int seg = kt >> kShift;
            const __half* bp = (seg == 0) ? B0 : (seg == 1) ? B1 : (seg == 2) ? B2 : B3;
            ktl = kt - (seg << kShift);
            Bb = bp + (size_t)bn * ldB;
        }
#pragma unroll
        for (int j = 0; j < 16; j++) {
            int idx = tid + j * 128;
            int isB = idx >> 10;
            int un = idx & 1023;
            int row = un >> 3, c = un & 7;
            uint32_t base = sb + (uint32_t)s * STGB + (isB ? ASTG : 0u)
                          + (uint32_t)(row << 7) + ((uint32_t)(c ^ (row & 7)) << 4);
            if (!isB) {
                cpa16(base, A + (size_t)(bm + row) * ldA + kt * BKH + c * 8);
            } else if (bn + row < N) {
                cpa16(base, Bb + (size_t)row * ldB + ktl * BKH + c * 8);
            }
        }
    };

    float acc[4][8][4];
#pragma unroll
    for (int i = 0; i < 4; i++)
#pragma unroll
        for (int j = 0; j < 8; j++)
#pragma unroll
            for (int r = 0; r < 4; r++) acc[i][j][r] = 0.0f;

    int l7 = lane & 7;
    int sub = lane >> 3;
    int arow = (sub & 1) * 8 + l7;
    int ah   = sub >> 1;
    int bnl  = (sub >> 1) * 8 + l7;
    int bch  = sub & 1;
    uint32_t aBase = sb + (uint32_t)((wm * 64 + arow) << 7);
    uint32_t bBase = sb + ASTG + (uint32_t)((wn * 64 + bnl) << 7);

#pragma unroll
    for (int s = 0; s < NSTG - 1; s++) {
        if (s < KTz) load_stage(s, ktBeg + s);
        CPA_COMMIT();
    }

    int scomp = 0, sload = NSTG - 1;
    for (int t = 0; t < KTz; t++) {
        CPA_WAIT1();
        __syncthreads();
        int tn = t + NSTG - 1;
        if (tn < KTz) load_stage(sload, ktBeg + tn);
        CPA_COMMIT();

        uint32_t aS = aBase + (uint32_t)scomp * STGB;
        uint32_t bS = bBase + (uint32_t)scomp * STGB;
#pragma unroll
        for (int ks = 0; ks < 4; ks++) {
            uint32_t bf[4][4];
            uint32_t af[4][4];
#pragma unroll
            for (int ntp = 0; ntp < 4; ntp++)
                LDSM_X4(bf[ntp], bS + (uint32_t)(ntp * 2048) +
                                  ((uint32_t)((2 * ks + bch) ^ l7) << 4));
#pragma unroll
            for (int mt = 0; mt < 4; mt++)
                LDSM_X4(af[mt], aS + (uint32_t)(mt * 2048) +
                                 ((uint32_t)((2 * ks + ah) ^ l7) << 4));
#pragma unroll
            for (int mt = 0; mt < 4; mt++)
#pragma unroll
                for (int nt = 0; nt < 8; nt++)
                    mma_f16(acc[mt][nt], af[mt],
                            bf[nt >> 1][(nt & 1) * 2], bf[nt >> 1][(nt & 1) * 2 + 1]);
        }
        scomp = (scomp + 1 == NSTG) ? 0 : scomp + 1;
        sload = (sload + 1 == NSTG) ? 0 : sload + 1;
    }

    int evenN = ((N & 1) == 0);
#pragma unroll
    for (int mt = 0; mt < 4; mt++) {
        int r0 = bm + wm * 64 + mt * 16 + (lane >> 2);
        int r1 = r0 + 8;
#pragma unroll
        for (int nt = 0; nt < 8; nt++) {
            int n0 = bn + wn * 64 + nt * 8 + 2 * (lane & 3);
            const float* a = acc[mt][nt];
            float v00 = a[0], v01 = a[1], v10 = a[2], v11 = a[3];
            if (fmode == 2) {
                float2 f0 = __half22float2(*(const __half2*)(F + (size_t)r0 * ldF + n0));
                float2 f1 = __half22float2(*(const __half2*)(F + (size_t)r1 * ldF + n0));
                int e = n0 >> 13;
                float w0 = wdense[r0 * 4 + e], w1_ = wdense[r1 * 4 + e];
                v00 = w0 * (f0.x / (1.0f + __expf(-f0.x))) * v00;
                v01 = w0 * (f0.y / (1.0f + __expf(-f0.y))) * v01;
                v10 = w1_ * (f1.x / (1.0f + __expf(-f1.x))) * v10;
                v11 = w1_ * (f1.y / (1.0f + __expf(-f1.y))) * v11;
            }
            if (Ch) {
                *(__half2*)(Ch + (size_t)r0 * ldC + n0) = __floats2half2_rn(v00, v01);
                *(__half2*)(Ch + (size_t)r1 * ldC + n0) = __floats2half2_rn(v10, v11);
            } else if (evenN && n0 + 1 < N) {
                *(float2*)(Cf + (size_t)r0 * ldC + n0) = make_float2(v00, v01);
                *(float2*)(Cf + (size_t)r1 * ldC + n0) = make_float2(v10, v11);
            } else {
                if (n0 < N)     { Cf[(size_t)r0 * ldC + n0] = v00; Cf[(size_t)r1 * ldC + n0] = v10; }
                if (n0 + 1 < N) { Cf[(size_t)r0 * ldC + n0 + 1] = v01; Cf[(size_t)r1 * ldC + n0 + 1] = v11; }
            }
        }
    }
}

// ---------------- fused all-weights convert fp32 -> fp16, deep MLP ----------------
// segment boundaries in float4 units
#define SEG_DD   1048576u                     // kD*kD/4
#define B4       4194304u                     // end of 4 small weights
#define SEG_FD   16777216u                    // kNE*kF*kD/4
#define B5       20971520u
#define B6       37748736u
#define B7       54525952u
#define CVT_TOT  80257536u                    // + kVOC*kD/4 (25731584)

__global__ void __launch_bounds__(256) cvt_all(
    const float* __restrict__ wq, const float* __restrict__ wk,
    const float* __restrict__ wv, const float* __restrict__ wo,
    const float* __restrict__ w1, const float* __restrict__ w3,
    const float* __restrict__ w2, const float* __restrict__ hw,
    __half* __restrict__ wqh, __half* __restrict__ wkh,
    __half* __restrict__ wvh, __half* __restrict__ woh,
    __half* __restrict__ w1h, __half* __restrict__ w3h,
    __half* __restrict__ w2h, __half* __restrict__ hdh)
{
    uint32_t g = blockIdx.x * 256u + threadIdx.x;
    uint32_t T = gridDim.x * 256u;

    for (uint32_t b0 = g; b0 < CVT_TOT; b0 += 8u * T) {
        float4 v[8];
        __half* dp[8];
        uint32_t doff[8];
        int ok[8];
#pragma unroll
        for (int j = 0; j < 8; j++) {
            uint32_t i = b0 + (uint32_t)j * T;
            ok[j] = (i < CVT_TOT);
            if (ok[j]) {
                const float* s; __half* d; uint32_t off;
                if (i < B4) {
                    int k = i >> 20;
                    off = i & (SEG_DD - 1);
                    s = (k == 0) ? wq : (k == 1) ? wk : (k == 2) ? wv : wo;
                    d = (k == 0) ? wqh : (k == 1) ? wkh : (k == 2) ? wvh : woh;
                } else if (i < B5) { off = i - B4; s = w1; d = w1h; }
                else if (i < B6)   { off = i - B5; s = w3; d = w3h; }
                else if (i < B7)   { off = i - B6; s = w2; d = w2h; }
                else               { off = i - B7; s = hw; d = hdh; }
                v[j] = ((const float4*)s)[off];
                dp[j] = d; doff[j] = off;
            }
        }
#pragma unroll
        for (int j = 0; j < 8; j++) {
            if (ok[j]) {
                __half2 h0 = __floats2half2_rn(v[j].x, v[j].y);
                __half2 h1 = __floats2half2_rn(v[j].z, v[j].w);
                uint2 pk;
                pk.x = *reinterpret_cast<uint32_t*>(&h0);
                pk.y = *reinterpret_cast<uint32_t*>(&h1);
                ((uint2*)dp[j])[doff[j]] = pk;
            }
        }
    }
}

// ---------------- embed (half out) ----------------
__global__ void embed_kernel(const int* __restrict__ tok, const float* __restrict__ emb,
                             __half* __restrict__ X) {
    int i = blockIdx.x * blockDim.x + threadIdx.x;
    int t = i >> 11;
    int d = i & 2047;
    X[i] = __float2half_rn(emb[(size_t)tok[t] * kD + d]);
}

// ---------------- fused split-K reduce + RoPE -> half packed QKV ----------------
__global__ void reduce_rope(const float* __restrict__ P, __half* __restrict__ Q) {
    int i = blockIdx.x * blockDim.x + threadIdx.x;
    int col2 = i % (3 * kD / 2);
    int t = i / (3 * kD / 2);
    const size_t n = (size_t)kS * 3 * kD;
    float v0 = P[2 * (size_t)i]     + P[n + 2 * (size_t)i];
    float v1 = P[2 * (size_t)i + 1] + P[n + 2 * (size_t)i + 1];
    int d = col2 * 2;
    if (d < 2 * kD) {
        int p = (d & 63) >> 1;
        float inv = 1.0f / powf(10000.0f, (float)(2 * p) / 64.0f);
        float ang = (float)t * inv;
        float c = cosf(ang), s = sinf(ang);
        float r0 = v0 * c - v1 * s;
        float r1 = v0 * s + v1 * c;
        v0 = r0; v1 = r1;
    }
    ((__half2*)Q)[i] = __floats2half2_rn(v0, v1);
}

// ---------------- attention (fp32 compute, half IO, parallel softmax) ----------------
__global__ void attn_kernel(const __half* __restrict__ QKV, __half* __restrict__ O) {
    extern __shared__ float sm[];
    const int LD = 68;
    const int ldx = 3 * kD;
    float* Qt  = sm;
    float* KP  = Qt + 64 * LD;
    float* Vs  = KP + 64 * LD;
    float* den = Vs + 64 * LD;
    int qi = blockIdx.x;
    int h  = blockIdx.y;
    int tid = threadIdx.x;
    int tx = tid & 15, ty = tid >> 4;

    for (int it = tid; it < 512; it += 256) {
        int q = it >> 3;
        int c8 = (it & 7) << 3;
        uint4 raw = *(const uint4*)(QKV + (size_t)(qi * 64 + q) * ldx + h * kHD + c8);
        const __half2* hp = (const __half2*)&raw;
#pragma unroll
        for (int m = 0; m < 4; m++) {
            float2 f = __half22float2(hp[m]);
            Qt[(c8 + 2 * m) * LD + q] = f.x;
            Qt[(c8 + 2 * m + 1) * LD + q] = f.y;
        }
    }
    if (tid < 64) den[tid] = 0.0f;

    float o[4][4] = {};
    for (int j = 0; j <= qi; j++) {
        __syncthreads();
        for (int it = tid; it < 512; it += 256) {
            int r = it >> 3;
            int c8 = (it & 7) << 3;
            uint4 kraw = *(const uint4*)(QKV + kD + (size_t)(j * 64 + r) * ldx + h * kHD + c8);
            uint4 vraw = *(const uint4*)(QKV + 2 * kD + (size_t)(j * 64 + r) * ldx + h * kHD + c8);
            const __half2* kp = (const __half2*)&kraw;
            const __half2* vp = (const __half2*)&vraw;
#pragma unroll
            for (int m = 0; m < 4; m++) {
                float2 fk = __half22float2(kp[m]);
                KP[(c8 + 2 * m) * LD + r] = fk.x;
                KP[(c8 + 2 * m + 1) * LD + r] = fk.y;
                float2 fv = __half22float2(vp[m]);
                Vs[r * LD + c8 + 2 * m] = fv.x;
                Vs[r * LD + c8 + 2 * m + 1] = fv.y;
            }
        }
        __syncthreads();
        float s[4][4] = {};
#pragma unroll 8
        for (int d = 0; d < 64; d++) {
            float4 a = *(const float4*)&Qt[d * LD + (ty << 2)];
            float4 b = *(const float4*)&KP[d * LD + (tx << 2)];
            float av[4] = {a.x, a.y, a.z, a.w};
            float bv[4] = {b.x, b.y, b.z, b.w};
#pragma unroll
            for (int i = 0; i < 4; i++)
#pragma unroll
                for (int j2 = 0; j2 < 4; j2++) s[i][j2] += av[i] * bv[j2];
        }
        __syncthreads();
#pragma unroll
        for (int i = 0; i < 4; i++) {
#pragma unroll
            for (int j2 = 0; j2 < 4; j2++) {
                int q = ty * 4 + i;
                int kcol = tx * 4 + j2;
                float val = s[i][j2] * 0.125f;
                if (j == qi && kcol > q) val = -INFINITY;
                KP[kcol * LD + q] = val;
            }
        }
        __syncthreads();
        {
            int q = tid >> 2, part = tid & 3;
            float m = -INFINITY;
#pragma unroll
            for (int i = 0; i < 16; i++)
                m = fmaxf(m, KP[(part + 4 * i) * LD + q]);
            m = fmaxf(m, __shfl_xor_sync(0xFFFFFFFFu, m, 1));
            m = fmaxf(m, __shfl_xor_sync(0xFFFFFFFFu, m, 2));
            float ds = 0.0f;
#pragma unroll
            for (int i = 0; i < 16; i++) {
                int k2 = part + 4 * i;
                float p = __expf(KP[k2 * LD + q] - m);
                KP[k2 * LD + q] = p;
                ds += p;
            }
            ds += __shfl_xor_sync(0xFFFFFFFFu, ds, 1);
            ds += __shfl_xor_sync(0xFFFFFFFFu, ds, 2);
            if (part == 0) den[q] += ds;
        }
        __syncthreads();
#pragma unroll 8
        for (int k2 = 0; k2 < 64; k2++) {
            float4 a = *(const float4*)&KP[k2 * LD + (ty << 2)];
            float4 b = *(const float4*)&Vs[k2 * LD + (tx << 2)];
            float av[4] = {a.x, a.y, a.z, a.w};
            float bv[4] = {b.x, b.y, b.z, b.w};
#pragma unroll
            for (int i = 0; i < 4; i++)
#pragma unroll
                for (int j2 = 0; j2 < 4; j2++) o[i][j2] += av[i] * bv[j2];
        }
    }
    __syncthreads();
#pragma unroll
    for (int i = 0; i < 4; i++) {
        int q = ty * 4 + i;
        float dn = den[q] + 1e-6f;
#pragma unroll
        for (int j2 = 0; j2 < 4; j2++) {
            int d = tx * 4 + j2;
            O[(size_t)(qi * 64 + q) * kD + h * kHD + d] = __float2half_rn(o[i][j2] / dn);
        }
    }
}

// ---------------- fused: x = P0+P1+R (residual), then LayerNorm -> half ----------------
__global__ void ln_fused(const float* __restrict__ P, const __half* __restrict__ R,
                         const float* __restrict__ g, const float* __restrict__ b,
                         __half* __restrict__ Y) {
    __shared__ float buf[kD];
    __shared__ float red[256];
    __shared__ float s_mu, s_inv;
    int row = blockIdx.x;
    int tid = threadIdx.x;
    const float* p0 = P + (size_t)row * kD;
    const float* p1 = p0 + (size_t)kS * kD;
    const __half* r = R + (size_t)row * kD;
    float s = 0.0f;
    for (int i = tid; i < kD; i += 256) {
        float v = p0[i] + p1[i] + __half2float(r[i]);
        buf[i] = v;
        s += v;
    }
    red[tid] = s; __syncthreads();
    for (int st = 128; st > 0; st >>= 1) { if (tid < st) red[tid] += red[tid + st]; __syncthreads(); }
    if (tid == 0) s_mu = red[0] / (float)kD;
    __syncthreads();
    float mu = s_mu;
    float v = 0.0f;
    for (int i = tid; i < kD; i += 256) { float d = buf[i] - mu; v += d * d; }
    red[tid] = v; __syncthreads();
    for (int st = 128; st > 0; st >>= 1) { if (tid < st) red[tid] += red[tid + st]; __syncthreads(); }
    if (tid == 0) s_inv = 1.0f / sqrtf(red[0] / (float)kD + 1e-5f);
    __syncthreads();
    float inv = s_inv;
    for (int i = tid; i < kD; i += 256)
        Y[(size_t)row * kD + i] = __float2half_rn((buf[i] - mu) * inv * g[i] + b[i]);
}

// ---------------- fused: x = P0+P1+R, LN(ln2), LN(fin) -> half ----------------
__global__ void ln2x_fused(const float* __restrict__ P, const __half* __restrict__ R,
                           const float* __restrict__ g2, const float* __restrict__ b2,
                           const float* __restrict__ gf, const float* __restrict__ bf,
                           __half* __restrict__ Y) {
    __shared__ float buf[kD];
    __shared__ float red[256];
    __shared__ float s_mu, s_inv;
    int row = blockIdx.x;
    int tid = threadIdx.x;
    const float* p0 = P + (size_t)row * kD;
    const float* p1 = p0 + (size_t)kS * kD;
    const __half* r = R + (size_t)row * kD;
    float s = 0.0f;
    for (int i = tid; i < kD; i += 256) {
        float v = p0[i] + p1[i] + __half2float(r[i]);
        buf[i] = v;
        s += v;
    }
    red[tid] = s; __syncthreads();
    for (int st = 128; st > 0; st >>= 1) { if (tid < st) red[tid] += red[tid + st]; __syncthreads(); }
    if (tid == 0) s_mu = red[0] / (float)kD;
    __syncthreads();
    float mu = s_mu;
    float v = 0.0f;
    for (int i = tid; i < kD; i += 256) { float d = buf[i] - mu; v += d * d; }
    red[tid] = v; __syncthreads();
    for (int st = 128; st > 0; st >>= 1) { if (tid < st) red[tid] += red[tid + st]; __syncthreads(); }
    if (tid == 0) s_inv = 1.0f / sqrtf(red[0] / (float)kD + 1e-5f);
    __syncthreads();
    float inv = s_inv;
    for (int i = tid; i < kD; i += 256)
        buf[i] = (buf[i] - mu) * inv * g2[i] + b2[i];
    __syncthreads();
    s = 0.0f;
    for (int i = tid; i < kD; i += 256) s += buf[i];
    red[tid] = s; __syncthreads();
    for (int st = 128; st > 0; st >>= 1) { if (tid < st) red[tid] += red[tid + st]; __syncthreads(); }
    if (tid == 0) s_mu = red[0] / (float)kD;
    __syncthreads();
    mu = s_mu;
    v = 0.0f;
    for (int i = tid; i < kD; i += 256) { float d = buf[i] - mu; v += d * d; }
    red[tid] = v; __syncthreads();
    for (int st = 128; st > 0; st >>= 1) { if (tid < st) red[tid] += red[tid + st]; __syncthreads(); }
    if (tid == 0) s_inv = 1.0f / sqrtf(red[0] / (float)kD + 1e-5f);
    __syncthreads();
    inv = s_inv;
    for (int i = tid; i < kD; i += 256)
        Y[(size_t)row * kD + i] = __float2half_rn((buf[i] - mu) * inv * gf[i] + bf[i]);
}

// ---------------- gate (half X) ----------------
__global__ void gate_kernel(const __half* __restrict__ X, const float* __restrict__ GW,
                            float* __restrict__ wdense, float* __restrict__ varbuf) {
    int t = blockIdx.x;
    int tid = threadIdx.x;
    __shared__ float red[128];
    __shared__ float logits[4];
    const __half* x = X + (size_t)t * kD;
    float acc[4] = {0.f, 0.f, 0.f, 0.f};
    for (int d = tid; d < kD; d += 128) {
        float xv = __half2float(x[d]);
        acc[0] += xv * GW[0 * kD + d];
        acc[1] += xv * GW[1 * kD + d];
        acc[2] += xv * GW[2 * kD + d];
        acc[3] += xv * GW[3 * kD + d];
    }
    for (int e = 0; e < 4; e++) {
        red[tid] = acc[e]; __syncthreads();
        for (int st = 64; st > 0; st >>= 1) { if (tid < st) red[tid] += red[tid + st]; __syncthreads(); }
        if (tid == 0) logits[e] = red[0];
        __syncthreads();
    }
    if (tid == 0) {
        float l[4] = {logits[0], logits[1], logits[2], logits[3]};
        float mx = fmaxf(fmaxf(l[0], l[1]), fmaxf(l[2], l[3]));
        float pe[4], ps = 0.f;
        for (int e = 0; e < 4; e++) { pe[e] = expf(l[e] - mx); ps += pe[e]; }
        float pr[4];
        for (int e = 0; e < 4; e++) pr[e] = pe[e] / ps;
        int a = 0;
        for (int e = 1; e < 4; e++) if (pr[e] > pr[a]) a = e;
        int b2 = -1;
        for (int e = 0; e < 4; e++) { if (e == a) continue; if (b2 < 0 || pr[e] > pr[b2]) b2 = e; }
        float wsum = pr[a] + pr[b2];
        float w[4] = {0.f, 0.f, 0.f, 0.f};
        w[a] = pr[a] / wsum; w[b2] = pr[b2] / wsum;
        for (int e = 0; e < 4; e++) wdense[t * 4 + e] = w[e];
        float mu = 0.25f * (l[0] + l[1] + l[2] + l[3]);
        float vv = 0.f;
        for (int e = 0; e < 4; e++) { float d = l[e] - mu; vv += d * d; }
        varbuf[t] = vv / 3.0f;
    }
}

__global__ void aux_kernel(const float* __restrict__ varbuf, float* __restrict__ out) {
    __shared__ float red[256];
    int tid = threadIdx.x;
    float s = 0.f;
    for (int i = tid; i < kS; i += 256) s += varbuf[i];
    red[tid] = s; __syncthreads();
    for (int st = 128; st > 0; st >>= 1) { if (tid < st) red[tid] += red[tid + st]; __syncthreads(); }
    if (tid == 0) out[0] = red[0] / (float)kS;
}

// ---------------- launch ----------------
extern "C" void kernel_launch(void* const* d_in, const int* in_sizes, int n_in,
                              void* d_out, int out_size) {
    const int*   tokens = (const int*)d_in[0];
    const float* emb    = (const float*)d_in[1];
    const float* wq     = (const float*)d_in[2];
    const float* wk     = (const float*)d_in[3];
    const float* wv     = (const float*)d_in[4];
    const float* wo     = (const float*)d_in[5];
    const float* ln1_g  = (const float*)d_in[6];
    const float* ln1_b  = (const float*)d_in[7];
    const float* gate_w = (const float*)d_in[8];
    const float* w1     = (const float*)d_in[9];
    const float* w2     = (const float*)d_in[10];
    const float* w3     = (const float*)d_in[11];
    const float* ln2_g  = (const float*)d_in[12];
    const float* ln2_b  = (const float*)d_in[13];
    const float* fin_g  = (const float*)d_in[14];
    const float* fin_b  = (const float*)d_in[15];
    const float* head_w = (const float*)d_in[16];
    float* out = (float*)d_out;

    __half *wqh, *wkh, *wvh, *woh, *w1h, *w3h, *w2h, *hdh;
    __half *x0h, *qkvh, *oh, *xn1h, *hah, *hbh, *x4h;
    float *part, *wdense, *varbuf;
    cudaGetSymbolAddress((void**)&wqh, g_wqh);
    cudaGetSymbolAddress((void**)&wkh, g_wkh);
    cudaGetSymbolAddress((void**)&wvh, g_wvh);
    cudaGetSymbolAddress((void**)&woh, g_woh);
    cudaGetSymbolAddress((void**)&w1h, g_w1h);
    cudaGetSymbolAddress((void**)&w3h, g_w3h);
    cudaGetSymbolAddress((void**)&w2h, g_w2h);
    cudaGetSymbolAddress((void**)&hdh, g_hdh);
    cudaGetSymbolAddress((void**)&x0h,  g_x0h);
    cudaGetSymbolAddress((void**)&qkvh, g_qkvh);
    cudaGetSymbolAddress((void**)&oh,   g_oh);
    cudaGetSymbolAddress((void**)&xn1h, g_xn1h);
    cudaGetSymbolAddress((void**)&hah,  g_hah);
    cudaGetSymbolAddress((void**)&hbh,  g_hbh);
    cudaGetSymbolAddress((void**)&x4h,  g_x4h);
    cudaGetSymbolAddress((void**)&part, g_part);
    cudaGetSymbolAddress((void**)&wdense, g_wdense);
    cudaGetSymbolAddress((void**)&varbuf, g_var);

    const int SD = kS * kD;
    const int KFD = kF * kD;

    cudaFuncSetAttribute(gemm_h, cudaFuncAttributeMaxDynamicSharedMemorySize, GEMM_SMEM);

    // ---- single fused weight convert (all 8 tensors, deep MLP) ----
    cvt_all<<<1184, 256>>>(wq, wk, wv, wo, w1, w3, w2, head_w,
                           wqh, wkh, wvh, woh, w1h, w3h, w2h, hdh);

    // embed
    embed_kernel<<<SD / 256, 256>>>(tokens, emb, x0h);

    // QKV (split-K=2 -> fp32 partials); fused reduce + rope -> half qkv
    gemm_h<<<dim3(kS / 128, 48, 2), 128, GEMM_SMEM>>>(
        x0h, wqh, wkh, wvh, nullptr, part, nullptr,
        3 * kD, kD / BKH, kD, kD, 3 * kD,
        11, -1, kD / BKH / 2, (long long)kS * 3 * kD,
        0, nullptr, 0, nullptr);
    reduce_rope<<<(kS * 3 * kD / 2) / 256, 256>>>(part, qkvh);

    // attention
    int attn_smem = (3 * 64 * 68 + 64) * (int)sizeof(float);
    cudaFuncSetAttribute(attn_kernel, cudaFuncAttributeMaxDynamicSharedMemorySize, attn_smem);
    attn_kernel<<<dim3(kS / 64, kH), 256, attn_smem>>>(qkvh, oh);

    // wo (split-K=2) -> partials; fused reduce + residual + ln1 -> half xn1
    gemm_h<<<dim3(kS / 128, kD / 128, 2), 128, GEMM_SMEM>>>(
        oh, woh, nullptr, nullptr, nullptr, part, nullptr,
        kD, kD / BKH, kD, kD, kD,
        30, -1, kD / BKH / 2, (long long)SD,
        0, nullptr, 0, nullptr);
    ln_fused<<<kS, 256>>>(part, x0h, ln1_g, ln1_b, xn1h);

    // gate + aux
    gate_kernel<<<kS, 128>>>(xn1h, gate_w, wdense, varbuf);
    aux_kernel<<<1, 256>>>(varbuf, out + (size_t)out_size - 1);

    // MoE: all-expert w1 -> ha (half)
    gemm_h<<<dim3(kS / 128, 256), 128, GEMM_SMEM>>>(
        xn1h, w1h, w1h + (size_t)KFD, w1h + 2 * (size_t)KFD, w1h + 3 * (size_t)KFD,
        nullptr, hah, kNE * kF, kD / BKH, kD, kD, kNE * kF,
        13, -1, kD / BKH, 0,
        0, nullptr, 0, nullptr);

    // all-expert w3 with fused gate+silu epilogue -> hb (half)
    gemm_h<<<dim3(kS / 128, 256), 128, GEMM_SMEM>>>(
        xn1h, w3h, w3h + (size_t)KFD, w3h + 2 * (size_t)KFD, w3h + 3 * (size_t)KFD,
        nullptr, hbh, kNE * kF, kD / BKH, kD, kD, kNE * kF,
        13, -1, kD / BKH, 0,
        2, hah, kNE * kF, wdense);

    // fused 4-expert w2, K=32768, split-K=2 -> partials; fused reduce + residual + 2xLN -> x4
    gemm_h<<<dim3(kS / 128, kD / 128, 2), 128, GEMM_SMEM>>>(
        hbh, w2h, w2h + (size_t)KFD, w2h + 2 * (size_t)KFD, w2h + 3 * (size_t)KFD,
        part, nullptr, kD, (kNE * kF) / BKH, kNE * kF, kF, kD,
        30, 7, (kNE * kF) / BKH / 2, (long long)SD,
        0, nullptr, 0, nullptr);
    ln2x_fused<<<kS, 256>>>(part, xn1h, ln2_g, ln2_b, fin_g, fin_b, x4h);

    // LM head -> fp32 logits
    gemm_h<<<dim3(kS / 128, (kVOC + 127) / 128), 128, GEMM_SMEM>>>(
        x4h, hdh, nullptr, nullptr, nullptr, out, nullptr,
        kVOC, kD / BKH, kD, kD, kVOC,
        30, -1, kD / BKH, 0,
        0, nullptr, 0, nullptr);
}

// round 13
// speedup vs baseline: 1.0230x; 1.0230x over previous
#include <cuda_runtime.h>
#include <cuda_fp16.h>
#include <math.h>
#include <stdint.h>

// ---------------- constants ----------------
#define kS   1024
#define kD   2048
#define kH   32
#define kHD  64
#define kF   8192
#define kNE  4
#define kVOC 50257
#define ANS  4          // attention j-splits

// ---------------- scratch ----------------
__device__ __half g_wqh[kD*kD];
__device__ __half g_wkh[kD*kD];
__device__ __half g_wvh[kD*kD];
__device__ __half g_woh[kD*kD];
__device__ __half g_w1h[kNE*kF*kD];
__device__ __half g_w3h[kNE*kF*kD];
__device__ __half g_w2h[kNE*kD*kF];
__device__ __half g_hdh[kVOC*kD];
__device__ __half g_x0h [kS*kD];
__device__ __half g_qkvh[kS*3*kD];
__device__ __half g_oh  [kS*kD];
__device__ __half g_xn1h[kS*kD];
__device__ __half g_hah [kS*kNE*kF];
__device__ __half g_hbh [kS*kNE*kF];
__device__ __half g_x4h [kS*kD];
__device__ float g_part[2*kS*3*kD];   // also reused for ANS*kS*kD attention O partials
__device__ float g_den [ANS*kS*kH];
__device__ float g_wdense[kS*kNE];
__device__ float g_var[kS];

// ---------------- PTX helpers ----------------
__device__ __forceinline__ uint32_t smem_u32(const void* p) {
    uint32_t a;
    asm("{ .reg .u64 t; cvta.to.shared.u64 t, %1; cvt.u32.u64 %0, t; }" : "=r"(a) : "l"(p));
    return a;
}
__device__ __forceinline__ void cpa16(uint32_t dst, const void* src) {
    asm volatile("cp.async.cg.shared.global [%0], [%1], 16;" :: "r"(dst), "l"(src));
}
#define CPA_COMMIT() asm volatile("cp.async.commit_group;" ::: "memory")
#define CPA_WAIT1()  asm volatile("cp.async.wait_group 1;" ::: "memory")

#define LDSM_X4(r, addr) \
    asm volatile("ldmatrix.sync.aligned.m8n8.x4.shared.b16 {%0,%1,%2,%3}, [%4];" \
        : "=r"((r)[0]), "=r"((r)[1]), "=r"((r)[2]), "=r"((r)[3]) : "r"(addr))

__device__ __forceinline__ void mma_f16(float* c, const uint32_t* a, uint32_t b0, uint32_t b1) {
    asm volatile("mma.sync.aligned.m16n8k16.row.col.f32.f16.f16.f32 "
        "{%0,%1,%2,%3}, {%4,%5,%6,%7}, {%8,%9}, {%0,%1,%2,%3};"
        : "+f"(c[0]), "+f"(c[1]), "+f"(c[2]), "+f"(c[3])
        : "r"(a[0]), "r"(a[1]), "r"(a[2]), "r"(a[3]), "r"(b0), "r"(b1));
}

// ---------------- fp16 mma.sync NT GEMM: 128x128 tile, 4 warps (2x2), warp 64x64 ------
#define BM 128
#define BN 128
#define BKH 64
#define NSTG 3
#define ASTG 16384
#define STGB 32768
#define GEMM_SMEM (NSTG*STGB)

__global__ void __launch_bounds__(128, 2) gemm_h(
    const __half* __restrict__ A,
    const __half* __restrict__ B0, const __half* __restrict__ B1,
    const __half* __restrict__ B2, const __half* __restrict__ B3,
    float* __restrict__ Cf, __half* __restrict__ Ch,
    int N, int KT, int ldA, int ldB, int ldC,
    int nShift, int kShift, int ktPerZ, long long zStrideC,
    int fmode, const __half* __restrict__ F, int ldF,
    const float* __restrict__ wdense)
{
    extern __shared__ char smraw[];
    uint32_t sb = smem_u32(smraw);
    int tid = threadIdx.x, lane = tid & 31, wid = tid >> 5;
    int wm = wid >> 1, wn = wid & 1;
    int bm = blockIdx.x * BM, bn = blockIdx.y * BN;

    Cf += (long long)blockIdx.z * zStrideC;
    int ktBeg = blockIdx.z * ktPerZ;
    int KTz = KT - ktBeg; if (KTz > ktPerZ) KTz = ktPerZ;

    const __half* BnBase;
    {
        int seg = bn >> nShift;
        const __half* bp = (seg == 0) ? B0 : (seg == 1) ? B1 : (seg == 2) ? B2 : B3;
        BnBase = bp + (size_t)(bn - (seg << nShift)) * ldB;
    }

    auto load_stage = [&](int s, int kt) {
        int ktl = kt;
        const __half* Bb = BnBase;
        if (kShift >= 0) {
            int seg = kt >> kShift;
            const __half* bp = (seg == 0) ? B0 : (seg == 1) ? B1 : (seg == 2) ? B2 : B3;
            ktl = kt - (seg << kShift);
            Bb = bp + (size_t)bn * ldB;
        }
#pragma unroll
        for (int j = 0; j < 16; j++) {
            int idx = tid + j * 128;
            int isB = idx >> 10;
            int un = idx & 1023;
            int row = un >> 3, c = un & 7;
            uint32_t base = sb + (uint32_t)s * STGB + (isB ? ASTG : 0u)
                          + (uint32_t)(row << 7) + ((uint32_t)(c ^ (row & 7)) << 4);
            if (!isB) {
                cpa16(base, A + (size_t)(bm + row) * ldA + kt * BKH + c * 8);
            } else if (bn + row < N) {
                cpa16(base, Bb + (size_t)row * ldB + ktl * BKH + c * 8);
            }
        }
    };

    float acc[4][8][4];
#pragma unroll
    for (int i = 0; i < 4; i++)
#pragma unroll
        for (int j = 0; j < 8; j++)
#pragma unroll
            for (int r = 0; r < 4; r++) acc[i][j][r] = 0.0f;

    int l7 = lane & 7;
    int sub = lane >> 3;
    int arow = (sub & 1) * 8 + l7;
    int ah   = sub >> 1;
    int bnl  = (sub >> 1) * 8 + l7;
    int bch  = sub & 1;
    uint32_t aBase = sb + (uint32_t)((wm * 64 + arow) << 7);
    uint32_t bBase = sb + ASTG + (uint32_t)((wn * 64 + bnl) << 7);

#pragma unroll
    for (int s = 0; s < NSTG - 1; s++) {
        if (s < KTz) load_stage(s, ktBeg + s);
        CPA_COMMIT();
    }

    int scomp = 0, sload = NSTG - 1;
    for (int t = 0; t < KTz; t++) {
        CPA_WAIT1();
        __syncthreads();
        int tn = t + NSTG - 1;
        if (tn < KTz) load_stage(sload, ktBeg + tn);
        CPA_COMMIT();

        uint32_t aS = aBase + (uint32_t)scomp * STGB;
        uint32_t bS = bBase + (uint32_t)scomp * STGB;
#pragma unroll
        for (int ks = 0; ks < 4; ks++) {
            uint32_t bf[4][4];
            uint32_t af[4][4];
#pragma unroll
            for (int ntp = 0; ntp < 4; ntp++)
                LDSM_X4(bf[ntp], bS + (uint32_t)(ntp * 2048) +
                                  ((uint32_t)((2 * ks + bch) ^ l7) << 4));
#pragma unroll
            for (int mt = 0; mt < 4; mt++)
                LDSM_X4(af[mt], aS + (uint32_t)(mt * 2048) +
                                 ((uint32_t)((2 * ks + ah) ^ l7) << 4));
#pragma unroll
            for (int mt = 0; mt < 4; mt++)
#pragma unroll
                for (int nt = 0; nt < 8; nt++)
                    mma_f16(acc[mt][nt], af[mt],
                            bf[nt >> 1][(nt & 1) * 2], bf[nt >> 1][(nt & 1) * 2 + 1]);
        }
        scomp = (scomp + 1 == NSTG) ? 0 : scomp + 1;
        sload = (sload + 1 == NSTG) ? 0 : sload + 1;
    }

    int evenN = ((N & 1) == 0);
#pragma unroll
    for (int mt = 0; mt < 4; mt++) {
        int r0 = bm + wm * 64 + mt * 16 + (lane >> 2);
        int r1 = r0 + 8;
#pragma unroll
        for (int nt = 0; nt < 8; nt++) {
            int n0 = bn + wn * 64 + nt * 8 + 2 * (lane & 3);
            const float* a = acc[mt][nt];
            float v00 = a[0], v01 = a[1], v10 = a[2], v11 = a[3];
            if (fmode == 2) {
                float2 f0 = __half22float2(*(const __half2*)(F + (size_t)r0 * ldF + n0));
                float2 f1 = __half22float2(*(const __half2*)(F + (size_t)r1 * ldF + n0));
                int e = n0 >> 13;
                float w0 = wdense[r0 * 4 + e], w1_ = wdense[r1 * 4 + e];
                v00 = w0 * (f0.x / (1.0f + __expf(-f0.x))) * v00;
                v01 = w0 * (f0.y / (1.0f + __expf(-f0.y))) * v01;
                v10 = w1_ * (f1.x / (1.0f + __expf(-f1.x))) * v10;
                v11 = w1_ * (f1.y / (1.0f + __expf(-f1.y))) * v11;
            }
            if (Ch) {
                *(__half2*)(Ch + (size_t)r0 * ldC + n0) = __floats2half2_rn(v00, v01);
                *(__half2*)(Ch + (size_t)r1 * ldC + n0) = __floats2half2_rn(v10, v11);
            } else if (evenN && n0 + 1 < N) {
                *(float2*)(Cf + (size_t)r0 * ldC + n0) = make_float2(v00, v01);
                *(float2*)(Cf + (size_t)r1 * ldC + n0) = make_float2(v10, v11);
            } else {
                if (n0 < N)     { Cf[(size_t)r0 * ldC + n0] = v00; Cf[(size_t)r1 * ldC + n0] = v10; }
                if (n0 + 1 < N) { Cf[(size_t)r0 * ldC + n0 + 1] = v01; Cf[(size_t)r1 * ldC + n0 + 1] = v11; }
            }
        }
    }
}

// ---------------- weight convert fp32 -> fp16 (MLP=4 per thread) ----------------
__global__ void cvt_h(const float* __restrict__ in, __half* __restrict__ out, int n4) {
    int base = blockIdx.x * 1024 + threadIdx.x;
    float4 v[4];
    int ok[4];
#pragma unroll
    for (int j = 0; j < 4; j++) {
        int idx = base + j * 256;
        ok[j] = idx < n4;
        if (ok[j]) v[j] = ((const float4*)in)[idx];
    }
#pragma unroll
    for (int j = 0; j < 4; j++) {
        if (ok[j]) {
            __half2 h0 = __floats2half2_rn(v[j].x, v[j].y);
            __half2 h1 = __floats2half2_rn(v[j].z, v[j].w);
            uint2 pr;
            pr.x = *reinterpret_cast<uint32_t*>(&h0);
            pr.y = *reinterpret_cast<uint32_t*>(&h1);
            ((uint2*)out)[base + j * 256] = pr;
        }
    }
}

// ---------------- embed (half out) ----------------
__global__ void embed_kernel(const int* __restrict__ tok, const float* __restrict__ emb,
                             __half* __restrict__ X) {
    int i = blockIdx.x * blockDim.x + threadIdx.x;
    int t = i >> 11;
    int d = i & 2047;
    X[i] = __float2half_rn(emb[(size_t)tok[t] * kD + d]);
}

// ---------------- fused split-K reduce + RoPE -> half packed QKV ----------------
__global__ void reduce_rope(const float* __restrict__ P, __half* __restrict__ Q) {
    int i = blockIdx.x * blockDim.x + threadIdx.x;
    int col2 = i % (3 * kD / 2);
    int t = i / (3 * kD / 2);
    const size_t n = (size_t)kS * 3 * kD;
    float v0 = P[2 * (size_t)i]     + P[n + 2 * (size_t)i];
    float v1 = P[2 * (size_t)i + 1] + P[n + 2 * (size_t)i + 1];
    int d = col2 * 2;
    if (d < 2 * kD) {
        int p = (d & 63) >> 1;
        float inv = 1.0f / powf(10000.0f, (float)(2 * p) / 64.0f);
        float ang = (float)t * inv;
        float c = cosf(ang), s = sinf(ang);
        float r0 = v0 * c - v1 * s;
        float r1 = v0 * s + v1 * c;
        v0 = r0; v1 = r1;
    }
    ((__half2*)Q)[i] = __floats2half2_rn(v0, v1);
}

// ---------------- attention, j-split (exactly additive per reference semantics) -------
// block (qi, h, s): handles j = s, s+ANS, ..., <= qi. Emits fp32 partial O and den.
__global__ void attn_kernel(const __half* __restrict__ QKV,
                            float* __restrict__ Opart, float* __restrict__ denpart) {
    extern __shared__ float sm[];
    const int LD = 68;
    const int ldx = 3 * kD;
    float* Qt  = sm;
    float* KP  = Qt + 64 * LD;
    float* Vs  = KP + 64 * LD;
    float* den = Vs + 64 * LD;
    int qi = blockIdx.x;
    int h  = blockIdx.y;
    int sp = blockIdx.z;
    int tid = threadIdx.x;
    int tx = tid & 15, ty = tid >> 4;

    for (int it = tid; it < 512; it += 256) {
        int q = it >> 3;
        int c8 = (it & 7) << 3;
        uint4 raw = *(const uint4*)(QKV + (size_t)(qi * 64 + q) * ldx + h * kHD + c8);
        const __half2* hp = (const __half2*)&raw;
#pragma unroll
        for (int m = 0; m < 4; m++) {
            float2 f = __half22float2(hp[m]);
            Qt[(c8 + 2 * m) * LD + q] = f.x;
            Qt[(c8 + 2 * m + 1) * LD + q] = f.y;
        }
    }
    if (tid < 64) den[tid] = 0.0f;

    float o[4][4] = {};
    for (int j = sp; j <= qi; j += ANS) {
        __syncthreads();
        for (int it = tid; it < 512; it += 256) {
            int r = it >> 3;
            int c8 = (it & 7) << 3;
            uint4 kraw = *(const uint4*)(QKV + kD + (size_t)(j * 64 + r) * ldx + h * kHD + c8);
            uint4 vraw = *(const uint4*)(QKV + 2 * kD + (size_t)(j * 64 + r) * ldx + h * kHD + c8);
            const __half2* kp = (const __half2*)&kraw;
            const __half2* vp = (const __half2*)&vraw;
#pragma unroll
            for (int m = 0; m < 4; m++) {
                float2 fk = __half22float2(kp[m]);
                KP[(c8 + 2 * m) * LD + r] = fk.x;
                KP[(c8 + 2 * m + 1) * LD + r] = fk.y;
                float2 fv = __half22float2(vp[m]);
                Vs[r * LD + c8 + 2 * m] = fv.x;
                Vs[r * LD + c8 + 2 * m + 1] = fv.y;
            }
        }
        __syncthreads();
        float s[4][4] = {};
#pragma unroll 8
        for (int d = 0; d < 64; d++) {
            float4 a = *(const float4*)&Qt[d * LD + (ty << 2)];
            float4 b = *(const float4*)&KP[d * LD + (tx << 2)];
            float av[4] = {a.x, a.y, a.z, a.w};
            float bv[4] = {b.x, b.y, b.z, b.w};
#pragma unroll
            for (int i = 0; i < 4; i++)
#pragma unroll
                for (int j2 = 0; j2 < 4; j2++) s[i][j2] += av[i] * bv[j2];
        }
        __syncthreads();
#pragma unroll
        for (int i = 0; i < 4; i++) {
#pragma unroll
            for (int j2 = 0; j2 < 4; j2++) {
                int q = ty * 4 + i;
                int kcol = tx * 4 + j2;
                float val = s[i][j2] * 0.125f;
                if (j == qi && kcol > q) val = -INFINITY;
                KP[kcol * LD + q] = val;
            }
        }
        __syncthreads();
        {
            int q = tid >> 2, part = tid & 3;
            float m = -INFINITY;
#pragma unroll
            for (int i = 0; i < 16; i++)
                m = fmaxf(m, KP[(part + 4 * i) * LD + q]);
            m = fmaxf(m, __shfl_xor_sync(0xFFFFFFFFu, m, 1));
            m = fmaxf(m, __shfl_xor_sync(0xFFFFFFFFu, m, 2));
            float ds = 0.0f;
#pragma unroll
            for (int i = 0; i < 16; i++) {
                int k2 = part + 4 * i;
                float p = __expf(KP[k2 * LD + q] - m);
                KP[k2 * LD + q] = p;
                ds += p;
            }
            ds += __shfl_xor_sync(0xFFFFFFFFu, ds, 1);
            ds += __shfl_xor_sync(0xFFFFFFFFu, ds, 2);
            if (part == 0) den[q] += ds;
        }
        __syncthreads();
#pragma unroll 8
        for (int k2 = 0; k2 < 64; k2++) {
            float4 a = *(const float4*)&KP[k2 * LD + (ty << 2)];
            float4 b = *(const float4*)&Vs[k2 * LD + (tx << 2)];
            float av[4] = {a.x, a.y, a.z, a.w};
            float bv[4] = {b.x, b.y, b.z, b.w};
#pragma unroll
            for (int i = 0; i < 4; i++)
#pragma unroll
                for (int j2 = 0; j2 < 4; j2++) o[i][j2] += av[i] * bv[j2];
        }
    }
    __syncthreads();
    // write fp32 partials
    float* Op = Opart + (size_t)sp * kS * kD;
#pragma unroll
    for (int i = 0; i < 4; i++) {
        int q = ty * 4 + i;
#pragma unroll
        for (int j2 = 0; j2 < 4; j2++) {
            int d = tx * 4 + j2;
            Op[(size_t)(qi * 64 + q) * kD + h * kHD + d] = o[i][j2];
        }
    }
    if (tid < 64)
        denpart[(size_t)sp * kS * kH + (size_t)(qi * 64 + tid) * kH + h] = den[tid];
}

// combine: O = (sum_s Opart) / (sum_s den + 1e-6) -> half
__global__ void attn_combine(const float* __restrict__ Opart, const float* __restrict__ denpart,
                             __half* __restrict__ O) {
    int i = blockIdx.x * blockDim.x + threadIdx.x;   // [0, kS*kD)
    int t = i >> 11;
    int h = (i & 2047) >> 6;
    float o = 0.f, dn = 0.f;
#pragma unroll
    for (int s = 0; s < ANS; s++) {
        o  += Opart[(size_t)s * kS * kD + i];
        dn += denpart[(size_t)s * kS * kH + (size_t)t * kH + h];
    }
    O[i] = __float2half_rn(o / (dn + 1e-6f));
}

// ---------------- fused: x = P0+P1+R (residual), then LayerNorm -> half ----------------
__global__ void ln_fused(const float* __restrict__ P, const __half* __restrict__ R,
                         const float* __restrict__ g, const float* __restrict__ b,
                         __half* __restrict__ Y) {
    __shared__ float buf[kD];
    __shared__ float red[256];
    __shared__ float s_mu, s_inv;
    int row = blockIdx.x;
    int tid = threadIdx.x;
    const float* p0 = P + (size_t)row * kD;
    const float* p1 = p0 + (size_t)kS * kD;
    const __half* r = R + (size_t)row * kD;
    float s = 0.0f;
    for (int i = tid; i < kD; i += 256) {
        float v = p0[i] + p1[i] + __half2float(r[i]);
        buf[i] = v;
        s += v;
    }
    red[tid] = s; __syncthreads();
    for (int st = 128; st > 0; st >>= 1) { if (tid < st) red[tid] += red[tid + st]; __syncthreads(); }
    if (tid == 0) s_mu = red[0] / (float)kD;
    __syncthreads();
    float mu = s_mu;
    float v = 0.0f;
    for (int i = tid; i < kD; i += 256) { float d = buf[i] - mu; v += d * d; }
    red[tid] = v; __syncthreads();
    for (int st = 128; st > 0; st >>= 1) { if (tid < st) red[tid] += red[tid + st]; __syncthreads(); }
    if (tid == 0) s_inv = 1.0f / sqrtf(red[0] / (float)kD + 1e-5f);
    __syncthreads();
    float inv = s_inv;
    for (int i = tid; i < kD; i += 256)
        Y[(size_t)row * kD + i] = __float2half_rn((buf[i] - mu) * inv * g[i] + b[i]);
}

// ---------------- fused: x = P0+P1+R, LN(ln2), LN(fin) -> half ----------------
__global__ void ln2x_fused(const float* __restrict__ P, const __half* __restrict__ R,
                           const float* __restrict__ g2, const float* __restrict__ b2,
                           const float* __restrict__ gf, const float* __restrict__ bf,
                           __half* __restrict__ Y) {
    __shared__ float buf[kD];
    __shared__ float red[256];
    __shared__ float s_mu, s_inv;
    int row = blockIdx.x;
    int tid = threadIdx.x;
    const float* p0 = P + (size_t)row * kD;
    const float* p1 = p0 + (size_t)kS * kD;
    const __half* r = R + (size_t)row * kD;
    float s = 0.0f;
    for (int i = tid; i < kD; i += 256) {
        float v = p0[i] + p1[i] + __half2float(r[i]);
        buf[i] = v;
        s += v;
    }
    red[tid] = s; __syncthreads();
    for (int st = 128; st > 0; st >>= 1) { if (tid < st) red[tid] += red[tid + st]; __syncthreads(); }
    if (tid == 0) s_mu = red[0] / (float)kD;
    __syncthreads();
    float mu = s_mu;
    float v = 0.0f;
    for (int i = tid; i < kD; i += 256) { float d = buf[i] - mu; v += d * d; }
    red[tid] = v; __syncthreads();
    for (int st = 128; st > 0; st >>= 1) { if (tid < st) red[tid] += red[tid + st]; __syncthreads(); }
    if (tid == 0) s_inv = 1.0f / sqrtf(red[0] / (float)kD + 1e-5f);
    __syncthreads();
    float inv = s_inv;
    for (int i = tid; i < kD; i += 256)
        buf[i] = (buf[i] - mu) * inv * g2[i] + b2[i];
    __syncthreads();
    s = 0.0f;
    for (int i = tid; i < kD; i += 256) s += buf[i];
    red[tid] = s; __syncthreads();
    for (int st = 128; st > 0; st >>= 1) { if (tid < st) red[tid] += red[tid + st]; __syncthreads(); }
    if (tid == 0) s_mu = red[0] / (float)kD;
    __syncthreads();
    mu = s_mu;
    v = 0.0f;
    for (int i = tid; i < kD; i += 256) { float d = buf[i] - mu; v += d * d; }
    red[tid] = v; __syncthreads();
    for (int st = 128; st > 0; st >>= 1) { if (tid < st) red[tid] += red[tid + st]; __syncthreads(); }
    if (tid == 0) s_inv = 1.0f / sqrtf(red[0] / (float)kD + 1e-5f);
    __syncthreads();
    inv = s_inv;
    for (int i = tid; i < kD; i += 256)
        Y[(size_t)row * kD + i] = __float2half_rn((buf[i] - mu) * inv * gf[i] + bf[i]);
}

// ---------------- gate (half X) ----------------
__global__ void gate_kernel(const __half* __restrict__ X, const float* __restrict__ GW,
                            float* __restrict__ wdense, float* __restrict__ varbuf) {
    int t = blockIdx.x;
    int tid = threadIdx.x;
    __shared__ float red[128];
    __shared__ float logits[4];
    const __half* x = X + (size_t)t * kD;
    float acc[4] = {0.f, 0.f, 0.f, 0.f};
    for (int d = tid; d < kD; d += 128) {
        float xv = __half2float(x[d]);
        acc[0] += xv * GW[0 * kD + d];
        acc[1] += xv * GW[1 * kD + d];
        acc[2] += xv * GW[2 * kD + d];
        acc[3] += xv * GW[3 * kD + d];
    }
    for (int e = 0; e < 4; e++) {
        red[tid] = acc[e]; __syncthreads();
        for (int st = 64; st > 0; st >>= 1) { if (tid < st) red[tid] += red[tid + st]; __syncthreads(); }
        if (tid == 0) logits[e] = red[0];
        __syncthreads();
    }
    if (tid == 0) {
        float l[4] = {logits[0], logits[1], logits[2], logits[3]};
        float mx = fmaxf(fmaxf(l[0], l[1]), fmaxf(l[2], l[3]));
        float pe[4], ps = 0.f;
        for (int e = 0; e < 4; e++) { pe[e] = expf(l[e] - mx); ps += pe[e]; }
        float pr[4];
        for (int e = 0; e < 4; e++) pr[e] = pe[e] / ps;
        int a = 0;
        for (int e = 1; e < 4; e++) if (pr[e] > pr[a]) a = e;
        int b2 = -1;
        for (int e = 0; e < 4; e++) { if (e == a) continue; if (b2 < 0 || pr[e] > pr[b2]) b2 = e; }
        float wsum = pr[a] + pr[b2];
        float w[4] = {0.f, 0.f, 0.f, 0.f};
        w[a] = pr[a] / wsum; w[b2] = pr[b2] / wsum;
        for (int e = 0; e < 4; e++) wdense[t * 4 + e] = w[e];
        float mu = 0.25f * (l[0] + l[1] + l[2] + l[3]);
        float vv = 0.f;
        for (int e = 0; e < 4; e++) { float d = l[e] - mu; vv += d * d; }
        varbuf[t] = vv / 3.0f;
    }
}

__global__ void aux_kernel(const float* __restrict__ varbuf, float* __restrict__ out) {
    __shared__ float red[256];
    int tid = threadIdx.x;
    float s = 0.f;
    for (int i = tid; i < kS; i += 256) s += varbuf[i];
    red[tid] = s; __syncthreads();
    for (int st = 128; st > 0; st >>= 1) { if (tid < st) red[tid] += red[tid + st]; __syncthreads(); }
    if (tid == 0) out[0] = red[0] / (float)kS;
}

// ---------------- launch ----------------
extern "C" void kernel_launch(void* const* d_in, const int* in_sizes, int n_in,
                              void* d_out, int out_size) {
    const int*   tokens = (const int*)d_in[0];
    const float* emb    = (const float*)d_in[1];
    const float* wq     = (const float*)d_in[2];
    const float* wk     = (const float*)d_in[3];
    const float* wv     = (const float*)d_in[4];
    const float* wo     = (const float*)d_in[5];
    const float* ln1_g  = (const float*)d_in[6];
    const float* ln1_b  = (const float*)d_in[7];
    const float* gate_w = (const float*)d_in[8];
    const float* w1     = (const float*)d_in[9];
    const float* w2     = (const float*)d_in[10];
    const float* w3     = (const float*)d_in[11];
    const float* ln2_g  = (const float*)d_in[12];
    const float* ln2_b  = (const float*)d_in[13];
    const float* fin_g  = (const float*)d_in[14];
    const float* fin_b  = (const float*)d_in[15];
    const float* head_w = (const float*)d_in[16];
    float* out = (float*)d_out;

    __half *wqh, *wkh, *wvh, *woh, *w1h, *w3h, *w2h, *hdh;
    __half *x0h, *qkvh, *oh, *xn1h, *hah, *hbh, *x4h;
    float *part, *denp, *wdense, *varbuf;
    cudaGetSymbolAddress((void**)&wqh, g_wqh);
    cudaGetSymbolAddress((void**)&wkh, g_wkh);
    cudaGetSymbolAddress((void**)&wvh, g_wvh);
    cudaGetSymbolAddress((void**)&woh, g_woh);
    cudaGetSymbolAddress((void**)&w1h, g_w1h);
    cudaGetSymbolAddress((void**)&w3h, g_w3h);
    cudaGetSymbolAddress((void**)&w2h, g_w2h);
    cudaGetSymbolAddress((void**)&hdh, g_hdh);
    cudaGetSymbolAddress((void**)&x0h,  g_x0h);
    cudaGetSymbolAddress((void**)&qkvh, g_qkvh);
    cudaGetSymbolAddress((void**)&oh,   g_oh);
    cudaGetSymbolAddress((void**)&xn1h, g_xn1h);
    cudaGetSymbolAddress((void**)&hah,  g_hah);
    cudaGetSymbolAddress((void**)&hbh,  g_hbh);
    cudaGetSymbolAddress((void**)&x4h,  g_x4h);
    cudaGetSymbolAddress((void**)&part, g_part);
    cudaGetSymbolAddress((void**)&denp, g_den);
    cudaGetSymbolAddress((void**)&wdense, g_wdense);
    cudaGetSymbolAddress((void**)&varbuf, g_var);

    const int SD = kS * kD;
    const int KFD = kF * kD;

    cudaFuncSetAttribute(gemm_h, cudaFuncAttributeMaxDynamicSharedMemorySize, GEMM_SMEM);

    // ---- convert weights to fp16 (separate per-tensor launches; measured fastest) ----
    {
        int nDD = kD * kD / 4;
        cvt_h<<<(nDD + 1023) / 1024, 256>>>(wq, wqh, nDD);
        cvt_h<<<(nDD + 1023) / 1024, 256>>>(wk, wkh, nDD);
        cvt_h<<<(nDD + 1023) / 1024, 256>>>(wv, wvh, nDD);
        cvt_h<<<(nDD + 1023) / 1024, 256>>>(wo, woh, nDD);
        int nFD = kNE * KFD / 4;
        cvt_h<<<(nFD + 1023) / 1024, 256>>>(w1, w1h, nFD);
        cvt_h<<<(nFD + 1023) / 1024, 256>>>(w3, w3h, nFD);
        cvt_h<<<(nFD + 1023) / 1024, 256>>>(w2, w2h, nFD);
        int nHD = kVOC * kD / 4;
        cvt_h<<<(nHD + 1023) / 1024, 256>>>(head_w, hdh, nHD);
    }

    // embed
    embed_kernel<<<SD / 256, 256>>>(tokens, emb, x0h);

    // QKV (split-K=2 -> fp32 partials); fused reduce + rope -> half qkv
    gemm_h<<<dim3(kS / 128, 48, 2), 128, GEMM_SMEM>>>(
        x0h, wqh, wkh, wvh, nullptr, part, nullptr,
        3 * kD, kD / BKH, kD, kD, 3 * kD,
        11, -1, kD / BKH / 2, (long long)kS * 3 * kD,
        0, nullptr, 0, nullptr);
    reduce_rope<<<(kS * 3 * kD / 2) / 256, 256>>>(part, qkvh);

    // attention: j-split partials into part (reused) + denp, then combine -> oh
    int attn_smem = (3 * 64 * 68 + 64) * (int)sizeof(float);
    cudaFuncSetAttribute(attn_kernel, cudaFuncAttributeMaxDynamicSharedMemorySize, attn_smem);
    attn_kernel<<<dim3(kS / 64, kH, ANS), 256, attn_smem>>>(qkvh, part, denp);
    attn_combine<<<SD / 256, 256>>>(part, denp, oh);

    // wo (split-K=2) -> partials; fused reduce + residual + ln1 -> half xn1
    gemm_h<<<dim3(kS / 128, kD / 128, 2), 128, GEMM_SMEM>>>(
        oh, woh, nullptr, nullptr, nullptr, part, nullptr,
        kD, kD / BKH, kD, kD, kD,
        30, -1, kD / BKH / 2, (long long)SD,
        0, nullptr, 0, nullptr);
    ln_fused<<<kS, 256>>>(part, x0h, ln1_g, ln1_b, xn1h);

    // gate + aux
    gate_kernel<<<kS, 128>>>(xn1h, gate_w, wdense, varbuf);
    aux_kernel<<<1, 256>>>(varbuf, out + (size_t)out_size - 1);

    // MoE: all-expert w1 -> ha (half)
    gemm_h<<<dim3(kS / 128, 256), 128, GEMM_SMEM>>>(
        xn1h, w1h, w1h + (size_t)KFD, w1h + 2 * (size_t)KFD, w1h + 3 * (size_t)KFD,
        nullptr, hah, kNE * kF, kD / BKH, kD, kD, kNE * kF,
        13, -1, kD / BKH, 0,
        0, nullptr, 0, nullptr);

    // all-expert w3 with fused gate+silu epilogue -> hb (half)
    gemm_h<<<dim3(kS / 128, 256), 128, GEMM_SMEM>>>(
        xn1h, w3h, w3h + (size_t)KFD, w3h + 2 * (size_t)KFD, w3h + 3 * (size_t)KFD,
        nullptr, hbh, kNE * kF, kD / BKH, kD, kD, kNE * kF,
        13, -1, kD / BKH, 0,
        2, hah, kNE * kF, wdense);

    // fused 4-expert w2, K=32768, split-K=2 -> partials; fused reduce + residual + 2xLN -> x4
    gemm_h<<<dim3(kS / 128, kD / 128, 2), 128, GEMM_SMEM>>>(
        hbh, w2h, w2h + (size_t)KFD, w2h + 2 * (size_t)KFD, w2h + 3 * (size_t)KFD,
        part, nullptr, kD, (kNE * kF) / BKH, kNE * kF, kF, kD,
        30, 7, (kNE * kF) / BKH / 2, (long long)SD,
        0, nullptr, 0, nullptr);
    ln2x_fused<<<kS, 256>>>(part, xn1h, ln2_g, ln2_b, fin_g, fin_b, x4h);

    // LM head -> fp32 logits
    gemm_h<<<dim3(kS / 128, (kVOC + 127) / 128), 128, GEMM_SMEM>>>(
        x4h, hdh, nullptr, nullptr, nullptr, out, nullptr,
        kVOC, kD / BKH, kD, kD, kVOC,
        30, -1, kD / BKH, 0,
        0, nullptr, 0, nullptr);
}

// round 14
// speedup vs baseline: 1.0299x; 1.0067x over previous
#include <cuda_runtime.h>
#include <cuda_fp16.h>
#include <math.h>
#include <stdint.h>

// ---------------- constants ----------------
#define kS   1024
#define kD   2048
#define kH   32
#define kHD  64
#define kF   8192
#define kNE  4
#define kVOC 50257
#define ANS  4          // attention j-splits

// ---------------- scratch ----------------
__device__ __half g_wqh[kD*kD];
__device__ __half g_wkh[kD*kD];
__device__ __half g_wvh[kD*kD];
__device__ __half g_woh[kD*kD];
__device__ __half g_w1h[kNE*kF*kD];
__device__ __half g_w3h[kNE*kF*kD];
__device__ __half g_w2h[kNE*kD*kF];
__device__ __half g_hdh[kVOC*kD];
__device__ __half g_x0h [kS*kD];
__device__ __half g_qkvh[kS*3*kD];
__device__ __half g_oh  [kS*kD];
__device__ __half g_xn1h[kS*kD];
__device__ __half g_hah [kS*kNE*kF];
__device__ __half g_hbh [kS*kNE*kF];
__device__ __half g_x4h [kS*kD];
__device__ float g_part[2*kS*3*kD];   // also reused for ANS*kS*kD attention O partials
__device__ float g_den [ANS*kS*kH];
__device__ float g_wdense[kS*kNE];
__device__ float g_var[kS];

// ---------------- PTX helpers ----------------
__device__ __forceinline__ uint32_t smem_u32(const void* p) {
    uint32_t a;
    asm("{ .reg .u64 t; cvta.to.shared.u64 t, %1; cvt.u32.u64 %0, t; }" : "=r"(a) : "l"(p));
    return a;
}
__device__ __forceinline__ void cpa16(uint32_t dst, const void* src) {
    asm volatile("cp.async.cg.shared.global [%0], [%1], 16;" :: "r"(dst), "l"(src));
}
#define CPA_COMMIT() asm volatile("cp.async.commit_group;" ::: "memory")
#define CPA_WAIT1()  asm volatile("cp.async.wait_group 1;" ::: "memory")

#define LDSM_X4(r, addr) \
    asm volatile("ldmatrix.sync.aligned.m8n8.x4.shared.b16 {%0,%1,%2,%3}, [%4];" \
        : "=r"((r)[0]), "=r"((r)[1]), "=r"((r)[2]), "=r"((r)[3]) : "r"(addr))

__device__ __forceinline__ void mma_f16(float* c, const uint32_t* a, uint32_t b0, uint32_t b1) {
    asm volatile("mma.sync.aligned.m16n8k16.row.col.f32.f16.f16.f32 "
        "{%0,%1,%2,%3}, {%4,%5,%6,%7}, {%8,%9}, {%0,%1,%2,%3};"
        : "+f"(c[0]), "+f"(c[1]), "+f"(c[2]), "+f"(c[3])
        : "r"(a[0]), "r"(a[1]), "r"(a[2]), "r"(a[3]), "r"(b0), "r"(b1));
}

// ---------------- fp16 mma.sync NT GEMM: 128x128 tile, 4 warps (2x2), warp 64x64 ------
#define BM 128
#define BN 128
#define BKH 64
#define NSTG 3
#define ASTG 16384
#define STGB 32768
#define GEMM_SMEM (NSTG*STGB)

__global__ void __launch_bounds__(128, 2) gemm_h(
    const __half* __restrict__ A,
    const __half* __restrict__ B0, const __half* __restrict__ B1,
    const __half* __restrict__ B2, const __half* __restrict__ B3,
    float* __restrict__ Cf, __half* __restrict__ Ch,
    int N, int KT, int ldA, int ldB, int ldC,
    int nShift, int kShift, int ktPerZ, long long zStrideC,
    int fmode, const __half* __restrict__ F, int ldF,
    const float* __restrict__ wdense)
{
    extern __shared__ char smraw[];
    uint32_t sb = smem_u32(smraw);
    int tid = threadIdx.x, lane = tid & 31, wid = tid >> 5;
    int wm = wid >> 1, wn = wid & 1;
    int bm = blockIdx.x * BM, bn = blockIdx.y * BN;

    Cf += (long long)blockIdx.z * zStrideC;
    int ktBeg = blockIdx.z * ktPerZ;
    int KTz = KT - ktBeg; if (KTz > ktPerZ) KTz = ktPerZ;

    const __half* BnBase;
    {
        int seg = bn >> nShift;
        const __half* bp = (seg == 0) ? B0 : (seg == 1) ? B1 : (seg == 2) ? B2 : B3;
        BnBase = bp + (size_t)(bn - (seg << nShift)) * ldB;
    }

    auto load_stage = [&](int s, int kt) {
        int ktl = kt;
        const __half* Bb = BnBase;
        if (kShift >= 0) {
            int seg = kt >> kShift;
            const __half* bp = (seg == 0) ? B0 : (seg == 1) ? B1 : (seg == 2) ? B2 : B3;
            ktl = kt - (seg << kShift);
            Bb = bp + (size_t)bn * ldB;
        }
#pragma unroll
        for (int j = 0; j < 16; j++) {
            int idx = tid + j * 128;
            int isB = idx >> 10;
            int un = idx & 1023;
            int row = un >> 3, c = un & 7;
            uint32_t base = sb + (uint32_t)s * STGB + (isB ? ASTG : 0u)
                          + (uint32_t)(row << 7) + ((uint32_t)(c ^ (row & 7)) << 4);
            if (!isB) {
                cpa16(base, A + (size_t)(bm + row) * ldA + kt * BKH + c * 8);
            } else if (bn + row < N) {
                cpa16(base, Bb + (size_t)row * ldB + ktl * BKH + c * 8);
            }
        }
    };

    float acc[4][8][4];
#pragma unroll
    for (int i = 0; i < 4; i++)
#pragma unroll
        for (int j = 0; j < 8; j++)
#pragma unroll
            for (int r = 0; r < 4; r++) acc[i][j][r] = 0.0f;

    int l7 = lane & 7;
    int sub = lane >> 3;
    int arow = (sub & 1) * 8 + l7;
    int ah   = sub >> 1;
    int bnl  = (sub >> 1) * 8 + l7;
    int bch  = sub & 1;
    uint32_t aBase = sb + (uint32_t)((wm * 64 + arow) << 7);
    uint32_t bBase = sb + ASTG + (uint32_t)((wn * 64 + bnl) << 7);

#pragma unroll
    for (int s = 0; s < NSTG - 1; s++) {
        if (s < KTz) load_stage(s, ktBeg + s);
        CPA_COMMIT();
    }

    int scomp = 0, sload = NSTG - 1;
    for (int t = 0; t < KTz; t++) {
        CPA_WAIT1();
        __syncthreads();
        int tn = t + NSTG - 1;
        if (tn < KTz) load_stage(sload, ktBeg + tn);
        CPA_COMMIT();

        uint32_t aS = aBase + (uint32_t)scomp * STGB;
        uint32_t bS = bBase + (uint32_t)scomp * STGB;
#pragma unroll
        for (int ks = 0; ks < 4; ks++) {
            uint32_t bf[4][4];
            uint32_t af[4][4];
#pragma unroll
            for (int ntp = 0; ntp < 4; ntp++)
                LDSM_X4(bf[ntp], bS + (uint32_t)(ntp * 2048) +
                                  ((uint32_t)((2 * ks + bch) ^ l7) << 4));
#pragma unroll
            for (int mt = 0; mt < 4; mt++)
                LDSM_X4(af[mt], aS + (uint32_t)(mt * 2048) +
                                 ((uint32_t)((2 * ks + ah) ^ l7) << 4));
#pragma unroll
            for (int mt = 0; mt < 4; mt++)
#pragma unroll
                for (int nt = 0; nt < 8; nt++)
                    mma_f16(acc[mt][nt], af[mt],
                            bf[nt >> 1][(nt & 1) * 2], bf[nt >> 1][(nt & 1) * 2 + 1]);
        }
        scomp = (scomp + 1 == NSTG) ? 0 : scomp + 1;
        sload = (sload + 1 == NSTG) ? 0 : sload + 1;
    }

    int evenN = ((N & 1) == 0);
#pragma unroll
    for (int mt = 0; mt < 4; mt++) {
        int r0 = bm + wm * 64 + mt * 16 + (lane >> 2);
        int r1 = r0 + 8;
#pragma unroll
        for (int nt = 0; nt < 8; nt++) {
            int n0 = bn + wn * 64 + nt * 8 + 2 * (lane & 3);
            const float* a = acc[mt][nt];
            float v00 = a[0], v01 = a[1], v10 = a[2], v11 = a[3];
            if (fmode == 2) {
                float2 f0 = __half22float2(*(const __half2*)(F + (size_t)r0 * ldF + n0));
                float2 f1 = __half22float2(*(const __half2*)(F + (size_t)r1 * ldF + n0));
                int e = n0 >> 13;
                float w0 = wdense[r0 * 4 + e], w1_ = wdense[r1 * 4 + e];
                v00 = w0 * (f0.x / (1.0f + __expf(-f0.x))) * v00;
                v01 = w0 * (f0.y / (1.0f + __expf(-f0.y))) * v01;
                v10 = w1_ * (f1.x / (1.0f + __expf(-f1.x))) * v10;
                v11 = w1_ * (f1.y / (1.0f + __expf(-f1.y))) * v11;
            }
            if (Ch) {
                *(__half2*)(Ch + (size_t)r0 * ldC + n0) = __floats2half2_rn(v00, v01);
                *(__half2*)(Ch + (size_t)r1 * ldC + n0) = __floats2half2_rn(v10, v11);
            } else if (evenN && n0 + 1 < N) {
                *(float2*)(Cf + (size_t)r0 * ldC + n0) = make_float2(v00, v01);
                *(float2*)(Cf + (size_t)r1 * ldC + n0) = make_float2(v10, v11);
            } else {
                if (n0 < N)     { Cf[(size_t)r0 * ldC + n0] = v00; Cf[(size_t)r1 * ldC + n0] = v10; }
                if (n0 + 1 < N) { Cf[(size_t)r0 * ldC + n0 + 1] = v01; Cf[(size_t)r1 * ldC + n0 + 1] = v11; }
            }
        }
    }
}

// ---------------- single-launch all-weights convert, block-contiguous chunks ----------
// chunk = 2048 float4 per block (32KB); segment chosen per-block (uniform branch).
// Segment sizes (float4): 4x 1048576 | 16777216 | 16777216 | 16777216 | 25731584 (head last)
#define SEG_DD   1048576u
#define B4       4194304u
#define B5       20971520u
#define B6       37748736u
#define B7       54525952u
#define CVT_TOT  80257536u
#define CVT_BLKS ((CVT_TOT + 2047u) / 2048u)   // 39188

__global__ void __launch_bounds__(256) cvt_all2(
    const float* __restrict__ wq, const float* __restrict__ wk,
    const float* __restrict__ wv, const float* __restrict__ wo,
    const float* __restrict__ w1, const float* __restrict__ w3,
    const float* __restrict__ w2, const float* __restrict__ hw,
    __half* __restrict__ wqh, __half* __restrict__ wkh,
    __half* __restrict__ wvh, __half* __restrict__ woh,
    __half* __restrict__ w1h, __half* __restrict__ w3h,
    __half* __restrict__ w2h, __half* __restrict__ hdh)
{
    uint32_t base = blockIdx.x * 2048u;
    const float* s; __half* d; uint32_t off; uint32_t segRem;
    if (base < B4) {
        int k = base >> 20;
        off = base & (SEG_DD - 1);
        s = (k == 0) ? wq : (k == 1) ? wk : (k == 2) ? wv : wo;
        d = (k == 0) ? wqh : (k == 1) ? wkh : (k == 2) ? wvh : woh;
        segRem = SEG_DD - off;
    } else if (base < B5) { off = base - B4; s = w1; d = w1h; segRem = B5 - base; }
    else if (base < B6)   { off = base - B5; s = w3; d = w3h; segRem = B6 - base; }
    else if (base < B7)   { off = base - B6; s = w2; d = w2h; segRem = B7 - base; }
    else                  { off = base - B7; s = hw; d = hdh; segRem = CVT_TOT - base; }

    uint32_t o0 = off + threadIdx.x;
    if (segRem >= 2048u) {
        float4 v[8];
#pragma unroll
        for (int j = 0; j < 8; j++) v[j] = ((const float4*)s)[o0 + j * 256u];
#pragma unroll
        for (int j = 0; j < 8; j++) {
            __half2 h0 = __floats2half2_rn(v[j].x, v[j].y);
            __half2 h1 = __floats2half2_rn(v[j].z, v[j].w);
            uint2 pk;
            pk.x = *reinterpret_cast<uint32_t*>(&h0);
            pk.y = *reinterpret_cast<uint32_t*>(&h1);
            ((uint2*)d)[o0 + j * 256u] = pk;
        }
    } else {
        // tail block (head segment end only)
#pragma unroll
        for (int j = 0; j < 8; j++) {
            uint32_t idx = o0 + j * 256u;
            if (idx - off < segRem) {
                float4 v = ((const float4*)s)[idx];
                __half2 h0 = __floats2half2_rn(v.x, v.y);
                __half2 h1 = __floats2half2_rn(v.z, v.w);
                uint2 pk;
                pk.x = *reinterpret_cast<uint32_t*>(&h0);
                pk.y = *reinterpret_cast<uint32_t*>(&h1);
                ((uint2*)d)[idx] = pk;
            }
        }
    }
}

// ---------------- embed (half out) ----------------
__global__ void embed_kernel(const int* __restrict__ tok, const float* __restrict__ emb,
                             __half* __restrict__ X) {
    int i = blockIdx.x * blockDim.x + threadIdx.x;
    int t = i >> 11;
    int d = i & 2047;
    X[i] = __float2half_rn(emb[(size_t)tok[t] * kD + d]);
}

// ---------------- fused split-K reduce + RoPE -> half packed QKV ----------------
__global__ void reduce_rope(const float* __restrict__ P, __half* __restrict__ Q) {
    int i = blockIdx.x * blockDim.x + threadIdx.x;
    int col2 = i % (3 * kD / 2);
    int t = i / (3 * kD / 2);
    const size_t n = (size_t)kS * 3 * kD;
    float v0 = P[2 * (size_t)i]     + P[n + 2 * (size_t)i];
    float v1 = P[2 * (size_t)i + 1] + P[n + 2 * (size_t)i + 1];
    int d = col2 * 2;
    if (d < 2 * kD) {
        int p = (d & 63) >> 1;
        float inv = 1.0f / powf(10000.0f, (float)(2 * p) / 64.0f);
        float ang = (float)t * inv;
        float c = cosf(ang), s = sinf(ang);
        float r0 = v0 * c - v1 * s;
        float r1 = v0 * s + v1 * c;
        v0 = r0; v1 = r1;
    }
    ((__half2*)Q)[i] = __floats2half2_rn(v0, v1);
}

// ---------------- attention, j-split (exactly additive per reference semantics) -------
__global__ void attn_kernel(const __half* __restrict__ QKV,
                            float* __restrict__ Opart, float* __restrict__ denpart) {
    extern __shared__ float sm[];
    const int LD = 68;
    const int ldx = 3 * kD;
    float* Qt  = sm;
    float* KP  = Qt + 64 * LD;
    float* Vs  = KP + 64 * LD;
    float* den = Vs + 64 * LD;
    int qi = blockIdx.x;
    int h  = blockIdx.y;
    int sp = blockIdx.z;
    int tid = threadIdx.x;
    int tx = tid & 15, ty = tid >> 4;

    for (int it = tid; it < 512; it += 256) {
        int q = it >> 3;
        int c8 = (it & 7) << 3;
        uint4 raw = *(const uint4*)(QKV + (size_t)(qi * 64 + q) * ldx + h * kHD + c8);
        const __half2* hp = (const __half2*)&raw;
#pragma unroll
        for (int m = 0; m < 4; m++) {
            float2 f = __half22float2(hp[m]);
            Qt[(c8 + 2 * m) * LD + q] = f.x;
            Qt[(c8 + 2 * m + 1) * LD + q] = f.y;
        }
    }
    if (tid < 64) den[tid] = 0.0f;

    float o[4][4] = {};
    for (int j = sp; j <= qi; j += ANS) {
        __syncthreads();
        for (int it = tid; it < 512; it += 256) {
            int r = it >> 3;
            int c8 = (it & 7) << 3;
            uint4 kraw = *(const uint4*)(QKV + kD + (size_t)(j * 64 + r) * ldx + h * kHD + c8);
            uint4 vraw = *(const uint4*)(QKV + 2 * kD + (size_t)(j * 64 + r) * ldx + h * kHD + c8);
            const __half2* kp = (const __half2*)&kraw;
            const __half2* vp = (const __half2*)&vraw;
#pragma unroll
            for (int m = 0; m < 4; m++) {
                float2 fk = __half22float2(kp[m]);
                KP[(c8 + 2 * m) * LD + r] = fk.x;
                KP[(c8 + 2 * m + 1) * LD + r] = fk.y;
                float2 fv = __half22float2(vp[m]);
                Vs[r * LD + c8 + 2 * m] = fv.x;
                Vs[r * LD + c8 + 2 * m + 1] = fv.y;
            }
        }
        __syncthreads();
        float s[4][4] = {};
#pragma unroll 8
        for (int d = 0; d < 64; d++) {
            float4 a = *(const float4*)&Qt[d * LD + (ty << 2)];
            float4 b = *(const float4*)&KP[d * LD + (tx << 2)];
            float av[4] = {a.x, a.y, a.z, a.w};
            float bv[4] = {b.x, b.y, b.z, b.w};
#pragma unroll
            for (int i = 0; i < 4; i++)
#pragma unroll
                for (int j2 = 0; j2 < 4; j2++) s[i][j2] += av[i] * bv[j2];
        }
        __syncthreads();
#pragma unroll
        for (int i = 0; i < 4; i++) {
#pragma unroll
            for (int j2 = 0; j2 < 4; j2++) {
                int q = ty * 4 + i;
                int kcol = tx * 4 + j2;
                float val = s[i][j2] * 0.125f;
                if (j == qi && kcol > q) val = -INFINITY;
                KP[kcol * LD + q] = val;
            }
        }
        __syncthreads();
        {
            int q = tid >> 2, part = tid & 3;
            float m = -INFINITY;
#pragma unroll
            for (int i = 0; i < 16; i++)
                m = fmaxf(m, KP[(part + 4 * i) * LD + q]);
            m = fmaxf(m, __shfl_xor_sync(0xFFFFFFFFu, m, 1));
            m = fmaxf(m, __shfl_xor_sync(0xFFFFFFFFu, m, 2));
            float ds = 0.0f;
#pragma unroll
            for (int i = 0; i < 16; i++) {
                int k2 = part + 4 * i;
                float p = __expf(KP[k2 * LD + q] - m);
                KP[k2 * LD + q] = p;
                ds += p;
            }
            ds += __shfl_xor_sync(0xFFFFFFFFu, ds, 1);
            ds += __shfl_xor_sync(0xFFFFFFFFu, ds, 2);
            if (part == 0) den[q] += ds;
        }
        __syncthreads();
#pragma unroll 8
        for (int k2 = 0; k2 < 64; k2++) {
            float4 a = *(const float4*)&KP[k2 * LD + (ty << 2)];
            float4 b = *(const float4*)&Vs[k2 * LD + (tx << 2)];
            float av[4] = {a.x, a.y, a.z, a.w};
            float bv[4] = {b.x, b.y, b.z, b.w};
#pragma unroll
            for (int i = 0; i < 4; i++)
#pragma unroll
                for (int j2 = 0; j2 < 4; j2++) o[i][j2] += av[i] * bv[j2];
        }
    }
    __syncthreads();
    float* Op = Opart + (size_t)sp * kS * kD;
#pragma unroll
    for (int i = 0; i < 4; i++) {
        int q = ty * 4 + i;
#pragma unroll
        for (int j2 = 0; j2 < 4; j2++) {
            int d = tx * 4 + j2;
            Op[(size_t)(qi * 64 + q) * kD + h * kHD + d] = o[i][j2];
        }
    }
    if (tid < 64)
        denpart[(size_t)sp * kS * kH + (size_t)(qi * 64 + tid) * kH + h] = den[tid];
}

__global__ void attn_combine(const float* __restrict__ Opart, const float* __restrict__ denpart,
                             __half* __restrict__ O) {
    int i = blockIdx.x * blockDim.x + threadIdx.x;
    int t = i >> 11;
    int h = (i & 2047) >> 6;
    float o = 0.f, dn = 0.f;
#pragma unroll
    for (int s = 0; s < ANS; s++) {
        o  += Opart[(size_t)s * kS * kD + i];
        dn += denpart[(size_t)s * kS * kH + (size_t)t * kH + h];
    }
    O[i] = __float2half_rn(o / (dn + 1e-6f));
}

// ---------------- fused: x = P0+P1+R (residual), then LayerNorm -> half ----------------
__global__ void ln_fused(const float* __restrict__ P, const __half* __restrict__ R,
                         const float* __restrict__ g, const float* __restrict__ b,
                         __half* __restrict__ Y) {
    __shared__ float buf[kD];
    __shared__ float red[256];
    __shared__ float s_mu, s_inv;
    int row = blockIdx.x;
    int tid = threadIdx.x;
    const float* p0 = P + (size_t)row * kD;
    const float* p1 = p0 + (size_t)kS * kD;
    const __half* r = R + (size_t)row * kD;
    float s = 0.0f;
    for (int i = tid; i < kD; i += 256) {
        float v = p0[i] + p1[i] + __half2float(r[i]);
        buf[i] = v;
        s += v;
    }
    red[tid] = s; __syncthreads();
    for (int st = 128; st > 0; st >>= 1) { if (tid < st) red[tid] += red[tid + st]; __syncthreads(); }
    if (tid == 0) s_mu = red[0] / (float)kD;
    __syncthreads();
    float mu = s_mu;
    float v = 0.0f;
    for (int i = tid; i < kD; i += 256) { float d = buf[i] - mu; v += d * d; }
    red[tid] = v; __syncthreads();
    for (int st = 128; st > 0; st >>= 1) { if (tid < st) red[tid] += red[tid + st]; __syncthreads(); }
    if (tid == 0) s_inv = 1.0f / sqrtf(red[0] / (float)kD + 1e-5f);
    __syncthreads();
    float inv = s_inv;
    for (int i = tid; i < kD; i += 256)
        Y[(size_t)row * kD + i] = __float2half_rn((buf[i] - mu) * inv * g[i] + b[i]);
}

// ---------------- fused: x = P0+P1+R, LN(ln2), LN(fin) -> half ----------------
__global__ void ln2x_fused(const float* __restrict__ P, const __half* __restrict__ R,
                           const float* __restrict__ g2, const float* __restrict__ b2,
                           const float* __restrict__ gf, const float* __restrict__ bf,
                           __half* __restrict__ Y) {
    __shared__ float buf[kD];
    __shared__ float red[256];
    __shared__ float s_mu, s_inv;
    int row = blockIdx.x;
    int tid = threadIdx.x;
    const float* p0 = P + (size_t)row * kD;
    const float* p1 = p0 + (size_t)kS * kD;
    const __half* r = R + (size_t)row * kD;
    float s = 0.0f;
    for (int i = tid; i < kD; i += 256) {
        float v = p0[i] + p1[i] + __half2float(r[i]);
        buf[i] = v;
        s += v;
    }
    red[tid] = s; __syncthreads();
    for (int st = 128; st > 0; st >>= 1) { if (tid < st) red[tid] += red[tid + st]; __syncthreads(); }
    if (tid == 0) s_mu = red[0] / (float)kD;
    __syncthreads();
    float mu = s_mu;
    float v = 0.0f;
    for (int i = tid; i < kD; i += 256) { float d = buf[i] - mu; v += d * d; }
    red[tid] = v; __syncthreads();
    for (int st = 128; st > 0; st >>= 1) { if (tid < st) red[tid] += red[tid + st]; __syncthreads(); }
    if (tid == 0) s_inv = 1.0f / sqrtf(red[0] / (float)kD + 1e-5f);
    __syncthreads();
    float inv = s_inv;
    for (int i = tid; i < kD; i += 256)
        buf[i] = (buf[i] - mu) * inv * g2[i] + b2[i];
    __syncthreads();
    s = 0.0f;
    for (int i = tid; i < kD; i += 256) s += buf[i];
    red[tid] = s; __syncthreads();
    for (int st = 128; st > 0; st >>= 1) { if (tid < st) red[tid] += red[tid + st]; __syncthreads(); }
    if (tid == 0) s_mu = red[0] / (float)kD;
    __syncthreads();
    mu = s_mu;
    v = 0.0f;
    for (int i = tid; i < kD; i += 256) { float d = buf[i] - mu; v += d * d; }
    red[tid] = v; __syncthreads();
    for (int st = 128; st > 0; st >>= 1) { if (tid < st) red[tid] += red[tid + st]; __syncthreads(); }
    if (tid == 0) s_inv = 1.0f / sqrtf(red[0] / (float)kD + 1e-5f);
    __syncthreads();
    inv = s_inv;
    for (int i = tid; i < kD; i += 256)
        Y[(size_t)row * kD + i] = __float2half_rn((buf[i] - mu) * inv * gf[i] + bf[i]);
}

// ---------------- gate (half X) ----------------
__global__ void gate_kernel(const __half* __restrict__ X, const float* __restrict__ GW,
                            float* __restrict__ wdense, float* __restrict__ varbuf) {
    int t = blockIdx.x;
    int tid = threadIdx.x;
    __shared__ float red[128];
    __shared__ float logits[4];
    const __half* x = X + (size_t)t * kD;
    float acc[4] = {0.f, 0.f, 0.f, 0.f};
    for (int d = tid; d < kD; d += 128) {
        float xv = __half2float(x[d]);
        acc[0] += xv * GW[0 * kD + d];
        acc[1] += xv * GW[1 * kD + d];
        acc[2] += xv * GW[2 * kD + d];
        acc[3] += xv * GW[3 * kD + d];
    }
    for (int e = 0; e < 4; e++) {
        red[tid] = acc[e]; __syncthreads();
        for (int st = 64; st > 0; st >>= 1) { if (tid < st) red[tid] += red[tid + st]; __syncthreads(); }
        if (tid == 0) logits[e] = red[0];
        __syncthreads();
    }
    if (tid == 0) {
        float l[4] = {logits[0], logits[1], logits[2], logits[3]};
        float mx = fmaxf(fmaxf(l[0], l[1]), fmaxf(l[2], l[3]));
        float pe[4], ps = 0.f;
        for (int e = 0; e < 4; e++) { pe[e] = expf(l[e] - mx); ps += pe[e]; }
        float pr[4];
        for (int e = 0; e < 4; e++) pr[e] = pe[e] / ps;
        int a = 0;
        for (int e = 1; e < 4; e++) if (pr[e] > pr[a]) a = e;
        int b2 = -1;
        for (int e = 0; e < 4; e++) { if (e == a) continue; if (b2 < 0 || pr[e] > pr[b2]) b2 = e; }
        float wsum = pr[a] + pr[b2];
        float w[4] = {0.f, 0.f, 0.f, 0.f};
        w[a] = pr[a] / wsum; w[b2] = pr[b2] / wsum;
        for (int e = 0; e < 4; e++) wdense[t * 4 + e] = w[e];
        float mu = 0.25f * (l[0] + l[1] + l[2] + l[3]);
        float vv = 0.f;
        for (int e = 0; e < 4; e++) { float d = l[e] - mu; vv += d * d; }
        varbuf[t] = vv / 3.0f;
    }
}

__global__ void aux_kernel(const float* __restrict__ varbuf, float* __restrict__ out) {
    __shared__ float red[256];
    int tid = threadIdx.x;
    float s = 0.f;
    for (int i = tid; i < kS; i += 256) s += varbuf[i];
    red[tid] = s; __syncthreads();
    for (int st = 128; st > 0; st >>= 1) { if (tid < st) red[tid] += red[tid + st]; __syncthreads(); }
    if (tid == 0) out[0] = red[0] / (float)kS;
}

// ---------------- launch ----------------
extern "C" void kernel_launch(void* const* d_in, const int* in_sizes, int n_in,
                              void* d_out, int out_size) {
    const int*   tokens = (const int*)d_in[0];
    const float* emb    = (const float*)d_in[1];
    const float* wq     = (const float*)d_in[2];
    const float* wk     = (const float*)d_in[3];
    const float* wv     = (const float*)d_in[4];
    const float* wo     = (const float*)d_in[5];
    const float* ln1_g  = (const float*)d_in[6];
    const float* ln1_b  = (const float*)d_in[7];
    const float* gate_w = (const float*)d_in[8];
    const float* w1     = (const float*)d_in[9];
    const float* w2     = (const float*)d_in[10];
    const float* w3     = (const float*)d_in[11];
    const float* ln2_g  = (const float*)d_in[12];
    const float* ln2_b  = (const float*)d_in[13];
    const float* fin_g  = (const float*)d_in[14];
    const float* fin_b  = (const float*)d_in[15];
    const float* head_w = (const float*)d_in[16];
    float* out = (float*)d_out;

    __half *wqh, *wkh, *wvh, *woh, *w1h, *w3h, *w2h, *hdh;
    __half *x0h, *qkvh, *oh, *xn1h, *hah, *hbh, *x4h;
    float *part, *denp, *wdense, *varbuf;
    cudaGetSymbolAddress((void**)&wqh, g_wqh);
    cudaGetSymbolAddress((void**)&wkh, g_wkh);
    cudaGetSymbolAddress((void**)&wvh, g_wvh);
    cudaGetSymbolAddress((void**)&woh, g_woh);
    cudaGetSymbolAddress((void**)&w1h, g_w1h);
    cudaGetSymbolAddress((void**)&w3h, g_w3h);
    cudaGetSymbolAddress((void**)&w2h, g_w2h);
    cudaGetSymbolAddress((void**)&hdh, g_hdh);
    cudaGetSymbolAddress((void**)&x0h,  g_x0h);
    cudaGetSymbolAddress((void**)&qkvh, g_qkvh);
    cudaGetSymbolAddress((void**)&oh,   g_oh);
    cudaGetSymbolAddress((void**)&xn1h, g_xn1h);
    cudaGetSymbolAddress((void**)&hah,  g_hah);
    cudaGetSymbolAddress((void**)&hbh,  g_hbh);
    cudaGetSymbolAddress((void**)&x4h,  g_x4h);
    cudaGetSymbolAddress((void**)&part, g_part);
    cudaGetSymbolAddress((void**)&denp, g_den);
    cudaGetSymbolAddress((void**)&wdense, g_wdense);
    cudaGetSymbolAddress((void**)&varbuf, g_var);

    const int SD = kS * kD;
    const int KFD = kF * kD;

    cudaFuncSetAttribute(gemm_h, cudaFuncAttributeMaxDynamicSharedMemorySize, GEMM_SMEM);

    // ---- single-launch weight convert (block-contiguous chunks, MLP=8) ----
    cvt_all2<<<CVT_BLKS, 256>>>(wq, wk, wv, wo, w1, w3, w2, head_w,
                                wqh, wkh, wvh, woh, w1h, w3h, w2h, hdh);

    // embed
    embed_kernel<<<SD / 256, 256>>>(tokens, emb, x0h);

    // QKV (split-K=2 -> fp32 partials); fused reduce + rope -> half qkv
    gemm_h<<<dim3(kS / 128, 48, 2), 128, GEMM_SMEM>>>(
        x0h, wqh, wkh, wvh, nullptr, part, nullptr,
        3 * kD, kD / BKH, kD, kD, 3 * kD,
        11, -1, kD / BKH / 2, (long long)kS * 3 * kD,
        0, nullptr, 0, nullptr);
    reduce_rope<<<(kS * 3 * kD / 2) / 256, 256>>>(part, qkvh);

    // attention: j-split partials into part (reused) + denp, then combine -> oh
    int attn_smem = (3 * 64 * 68 + 64) * (int)sizeof(float);
    cudaFuncSetAttribute(attn_kernel, cudaFuncAttributeMaxDynamicSharedMemorySize, attn_smem);
    attn_kernel<<<dim3(kS / 64, kH, ANS), 256, attn_smem>>>(qkvh, part, denp);
    attn_combine<<<SD / 256, 256>>>(part, denp, oh);

    // wo (split-K=2) -> partials; fused reduce + residual + ln1 -> half xn1
    gemm_h<<<dim3(kS / 128, kD / 128, 2), 128, GEMM_SMEM>>>(
        oh, woh, nullptr, nullptr, nullptr, part, nullptr,
        kD, kD / BKH, kD, kD, kD,
        30, -1, kD / BKH / 2, (long long)SD,
        0, nullptr, 0, nullptr);
    ln_fused<<<kS, 256>>>(part, x0h, ln1_g, ln1_b, xn1h);

    // gate + aux
    gate_kernel<<<kS, 128>>>(xn1h, gate_w, wdense, varbuf);
    aux_kernel<<<1, 256>>>(varbuf, out + (size_t)out_size - 1);

    // MoE: all-expert w1 -> ha (half)
    gemm_h<<<dim3(kS / 128, 256), 128, GEMM_SMEM>>>(
        xn1h, w1h, w1h + (size_t)KFD, w1h + 2 * (size_t)KFD, w1h + 3 * (size_t)KFD,
        nullptr, hah, kNE * kF, kD / BKH, kD, kD, kNE * kF,
        13, -1, kD / BKH, 0,
        0, nullptr, 0, nullptr);

    // all-expert w3 with fused gate+silu epilogue -> hb (half)
    gemm_h<<<dim3(kS / 128, 256), 128, GEMM_SMEM>>>(
        xn1h, w3h, w3h + (size_t)KFD, w3h + 2 * (size_t)KFD, w3h + 3 * (size_t)KFD,
        nullptr, hbh, kNE * kF, kD / BKH, kD, kD, kNE * kF,
        13, -1, kD / BKH, 0,
        2, hah, kNE * kF, wdense);

    // fused 4-expert w2, K=32768, split-K=2 -> partials; fused reduce + residual + 2xLN -> x4
    gemm_h<<<dim3(kS / 128, kD / 128, 2), 128, GEMM_SMEM>>>(
        hbh, w2h, w2h + (size_t)KFD, w2h + 2 * (size_t)KFD, w2h + 3 * (size_t)KFD,
        part, nullptr, kD, (kNE * kF) / BKH, kNE * kF, kF, kD,
        30, 7, (kNE * kF) / BKH / 2, (long long)SD,
        0, nullptr, 0, nullptr);
    ln2x_fused<<<kS, 256>>>(part, xn1h, ln2_g, ln2_b, fin_g, fin_b, x4h);

    // LM head -> fp32 logits
    gemm_h<<<dim3(kS / 128, (kVOC + 127) / 128), 128, GEMM_SMEM>>>(
        x4h, hdh, nullptr, nullptr, nullptr, out, nullptr,
        kVOC, kD / BKH, kD, kD, kVOC,
        30, -1, kD / BKH, 0,
        0, nullptr, 0, nullptr);
}